// round 5
// baseline (speedup 1.0000x reference)
#include <cuda_runtime.h>
#include <cuda_bf16.h>
#include <math.h>

// Problem constants
#define D_DIM 1024
#define B_DIM 32
#define NBLK  128      // persistent scan blocks (<=148 SMs, occupancy 1 => all co-resident)
#define COLS  8        // columns of W per scan block (NBLK*COLS == D_DIM)

// -------------------- device scratch (no cudaMalloc allowed) --------------------
__device__ float g_scale;
__device__ float g_Wsc[D_DIM * D_DIM];          // W_h * scale, row-major [e][d]
__device__ float g_hT[2][D_DIM * B_DIM];        // recurrent state, d-major [d][b], double-buffered
__device__ unsigned g_bar_cnt = 0;
__device__ volatile unsigned g_bar_gen = 0;

// -------------------- block-wide sum over 1024 threads --------------------
__device__ __forceinline__ float block_sum1024(float v) {
    __shared__ float sr[32];
    __shared__ float res;
    #pragma unroll
    for (int o = 16; o; o >>= 1) v += __shfl_xor_sync(0xffffffffu, v, o);
    if ((threadIdx.x & 31) == 0) sr[threadIdx.x >> 5] = v;
    __syncthreads();
    if (threadIdx.x < 32) {
        float t = sr[threadIdx.x];
        #pragma unroll
        for (int o = 16; o; o >>= 1) t += __shfl_xor_sync(0xffffffffu, t, o);
        if (threadIdx.x == 0) res = t;
    }
    __syncthreads();
    float out = res;
    __syncthreads();   // allow shared reuse on next call
    return out;
}

// -------------------- 1) spectral norm power iteration --------------------
// Matches reference exactly: u = u0/||u0||; 3x { v = W^T u; v/=(||v||+eps);
// u = W v; u/=(||u||+eps) }; sigma = |u . (W v_last)|; scale = 0.99/(sigma+eps)
__global__ void spectral_kernel(const float* __restrict__ Wh,
                                const float* __restrict__ u0) {
    __shared__ float su[D_DIM];
    __shared__ float sv[D_DIM];
    __shared__ float sraw[D_DIM];
    const int tid  = threadIdx.x;
    const int w    = tid >> 5;
    const int lane = tid & 31;

    // u = u0 / ||u0||   (no eps, per reference)
    float x0 = u0[tid];
    float n0 = sqrtf(block_sum1024(x0 * x0));
    su[tid] = x0 / n0;
    __syncthreads();

    for (int it = 0; it < 3; it++) {
        // v = W^T u : thread tid = column j (coalesced LDG down column)
        {
            float a = 0.f;
            const float* col = Wh + tid;
            #pragma unroll 4
            for (int i = 0; i < D_DIM; i++)
                a = fmaf(col[(size_t)i * D_DIM], su[i], a);
            float nrm = sqrtf(block_sum1024(a * a));
            sv[tid] = a / (nrm + 1e-8f);
            __syncthreads();
        }
        // u_raw = W v : each warp handles 32 rows, lanes stride columns (coalesced)
        {
            for (int s = 0; s < 32; s++) {
                int r = w * 32 + s;
                const float* row = Wh + (size_t)r * D_DIM;
                float a = 0.f;
                #pragma unroll 4
                for (int k = lane; k < D_DIM; k += 32)
                    a = fmaf(row[k], sv[k], a);
                #pragma unroll
                for (int o = 16; o; o >>= 1) a += __shfl_xor_sync(0xffffffffu, a, o);
                if (lane == 0) sraw[r] = a;
            }
            __syncthreads();
            float rv  = sraw[tid];
            float nrm = sqrtf(block_sum1024(rv * rv));
            su[tid] = rv / (nrm + 1e-8f);
            __syncthreads();
        }
    }
    // sigma = |u . (W v_last)| = |u . raw|
    float sg = block_sum1024(su[tid] * sraw[tid]);
    if (tid == 0) g_scale = 0.99f / (fabsf(sg) + 1e-8f);
}

// -------------------- 2) prep: scale W, transpose h0, copy h0 to output --------------------
__global__ void prep_kernel(const float* __restrict__ Wh,
                            const float* __restrict__ h0,
                            float* __restrict__ hout0) {
    const float s = g_scale;
    int i = blockIdx.x * blockDim.x + threadIdx.x;
    if (i < D_DIM * D_DIM) g_Wsc[i] = Wh[i] * s;
    if (i < B_DIM * D_DIM) {
        int b = i >> 10;          // h0 is [B][D]
        int d = i & (D_DIM - 1);
        g_hT[0][d * B_DIM + b] = h0[i];
        hout0[i] = h0[i];         // h[0] = h0
    }
}

// -------------------- 3) SGEMM: Wx[m][e] = sum_d X[m][d] * W[e][d] --------------------
// M = T*B (65536), N = K = 1024. BM=BN=128, BK=8, 256 threads, 8x8 micro-tile.
__global__ __launch_bounds__(256, 2)
void gemm_xwt_kernel(const float* __restrict__ X,
                     const float* __restrict__ W,
                     float* __restrict__ C) {
    __shared__ float As[8 * 128];
    __shared__ float Bs[8 * 128];
    const int bm = blockIdx.y * 128;
    const int bn = blockIdx.x * 128;
    const int tid = threadIdx.x;
    const int tx = tid & 15;
    const int ty = tid >> 4;
    const int lrow = tid >> 1;
    const int lcol = (tid & 1) * 4;

    const float* Xp = X + (size_t)(bm + lrow) * D_DIM + lcol;
    const float* Wp = W + (size_t)(bn + lrow) * D_DIM + lcol;

    float acc[8][8];
    #pragma unroll
    for (int i = 0; i < 8; i++)
        #pragma unroll
        for (int j = 0; j < 8; j++) acc[i][j] = 0.f;

    for (int k0 = 0; k0 < D_DIM; k0 += 8) {
        float4 av = *(const float4*)(Xp + k0);
        float4 bv = *(const float4*)(Wp + k0);
        __syncthreads();
        As[(lcol + 0) * 128 + lrow] = av.x;
        As[(lcol + 1) * 128 + lrow] = av.y;
        As[(lcol + 2) * 128 + lrow] = av.z;
        As[(lcol + 3) * 128 + lrow] = av.w;
        Bs[(lcol + 0) * 128 + lrow] = bv.x;
        Bs[(lcol + 1) * 128 + lrow] = bv.y;
        Bs[(lcol + 2) * 128 + lrow] = bv.z;
        Bs[(lcol + 3) * 128 + lrow] = bv.w;
        __syncthreads();
        #pragma unroll
        for (int k = 0; k < 8; k++) {
            float af[8], bf[8];
            *(float4*)(af)     = *(const float4*)&As[k * 128 + ty * 8];
            *(float4*)(af + 4) = *(const float4*)&As[k * 128 + ty * 8 + 4];
            *(float4*)(bf)     = *(const float4*)&Bs[k * 128 + tx * 8];
            *(float4*)(bf + 4) = *(const float4*)&Bs[k * 128 + tx * 8 + 4];
            #pragma unroll
            for (int i = 0; i < 8; i++)
                #pragma unroll
                for (int j = 0; j < 8; j++)
                    acc[i][j] = fmaf(af[i], bf[j], acc[i][j]);
        }
    }
    float* Cp = C + (size_t)(bm + ty * 8) * D_DIM + bn + tx * 8;
    #pragma unroll
    for (int i = 0; i < 8; i++) {
        float4 v0 = make_float4(acc[i][0], acc[i][1], acc[i][2], acc[i][3]);
        float4 v1 = make_float4(acc[i][4], acc[i][5], acc[i][6], acc[i][7]);
        *(float4*)(Cp + (size_t)i * D_DIM)     = v0;
        *(float4*)(Cp + (size_t)i * D_DIM + 4) = v1;
    }
}

// -------------------- 4) persistent scan kernel --------------------
// 128 blocks x 256 threads. Block owns 8 W rows (smem-resident for entire kernel).
// Warp w owns d-chunk [w*128, w*128+128): stages its h slice privately (no block
// sync before compute). Grid barrier per step via fence + atomic generation.
//
// smem floats: w_sm 8*1028 | h_sm 1024*32 | red 8*256 | hn 256 | b 8 | bg 8
#define W_PAD 1028
#define SMEM_FLOATS (8 * W_PAD + D_DIM * B_DIM + 8 * 256 + 256 + 8 + 8)

__global__ __launch_bounds__(256, 1)
void scan_kernel(float* __restrict__ wx_out,        // [T][B][D]: in = Wx, overwritten with out
                 float* __restrict__ hout,          // [T+1][B][D]
                 const float* __restrict__ bvec,
                 const float* __restrict__ bgvec,
                 int T) {
    extern __shared__ float sm[];
    float* w_sm  = sm;                       // 8 * W_PAD
    float* h_sm  = w_sm + 8 * W_PAD;         // 1024 * 32, layout [d][b]
    float* red   = h_sm + D_DIM * B_DIM;     // 8 warps * 256 outputs
    float* hn_sm = red + 8 * 256;            // 256
    float* bsm   = hn_sm + 256;              // 8
    float* bgsm  = bsm + 8;                  // 8

    const int tid = threadIdx.x;
    const int e0  = blockIdx.x * COLS;

    // load this block's 8 W rows into padded smem (conflict-free later)
    {
        const float4* src = (const float4*)(g_Wsc + (size_t)e0 * D_DIM);
        for (int i = tid; i < 2048; i += 256) {
            float4 v = src[i];
            int e = i >> 8;
            int d = (i & 255) * 4;
            *(float4*)&w_sm[e * W_PAD + d] = v;
        }
        if (tid < 8) { bsm[tid] = bvec[e0 + tid]; bgsm[tid] = bgvec[e0 + tid]; }
    }
    __syncthreads();

    const int w     = tid >> 5;
    const int lane  = tid & 31;
    const int epair = lane >> 3;
    const int bq    = lane & 7;
    const int eA    = 2 * epair;
    const int eB    = eA + 1;
    const float* wA = w_sm + eA * W_PAD;
    const float* wB = w_sm + eB * W_PAD;
    const int d0    = w * 128;

    unsigned gen = g_bar_gen;   // read before any barrier can complete -> uniform
    int par = 0;

    for (int t = 0; t < T; t++) {
        // ---- per-warp private stage of this warp's d-chunk (L2 -> smem) ----
        {
            const float4* src = (const float4*)g_hT[par];
            float4* dst = (float4*)h_sm;
            const int base = w * 1024;      // 128 d * 8 float4 per d
            #pragma unroll
            for (int i = 0; i < 32; i++) {
                int idx = base + lane + 32 * i;
                dst[idx] = __ldcg(&src[idx]);
            }
            __syncwarp();
        }
        // ---- partial dot products over the chunk: acc[e][4 b's] ----
        float4 accA = make_float4(0.f, 0.f, 0.f, 0.f);
        float4 accB = make_float4(0.f, 0.f, 0.f, 0.f);
        #pragma unroll 4
        for (int d = d0; d < d0 + 128; d += 4) {
            float4 wa = *(const float4*)(wA + d);
            float4 wb = *(const float4*)(wB + d);
            const float4* hp = (const float4*)h_sm + (size_t)d * 8 + bq;
            float4 h0v = hp[0], h1v = hp[8], h2v = hp[16], h3v = hp[24];
            accA.x = fmaf(wa.x, h0v.x, accA.x); accA.y = fmaf(wa.x, h0v.y, accA.y);
            accA.z = fmaf(wa.x, h0v.z, accA.z); accA.w = fmaf(wa.x, h0v.w, accA.w);
            accA.x = fmaf(wa.y, h1v.x, accA.x); accA.y = fmaf(wa.y, h1v.y, accA.y);
            accA.z = fmaf(wa.y, h1v.z, accA.z); accA.w = fmaf(wa.y, h1v.w, accA.w);
            accA.x = fmaf(wa.z, h2v.x, accA.x); accA.y = fmaf(wa.z, h2v.y, accA.y);
            accA.z = fmaf(wa.z, h2v.z, accA.z); accA.w = fmaf(wa.z, h2v.w, accA.w);
            accA.x = fmaf(wa.w, h3v.x, accA.x); accA.y = fmaf(wa.w, h3v.y, accA.y);
            accA.z = fmaf(wa.w, h3v.z, accA.z); accA.w = fmaf(wa.w, h3v.w, accA.w);
            accB.x = fmaf(wb.x, h0v.x, accB.x); accB.y = fmaf(wb.x, h0v.y, accB.y);
            accB.z = fmaf(wb.x, h0v.z, accB.z); accB.w = fmaf(wb.x, h0v.w, accB.w);
            accB.x = fmaf(wb.y, h1v.x, accB.x); accB.y = fmaf(wb.y, h1v.y, accB.y);
            accB.z = fmaf(wb.y, h1v.z, accB.z); accB.w = fmaf(wb.y, h1v.w, accB.w);
            accB.x = fmaf(wb.z, h2v.x, accB.x); accB.y = fmaf(wb.z, h2v.y, accB.y);
            accB.z = fmaf(wb.z, h2v.z, accB.z); accB.w = fmaf(wb.z, h2v.w, accB.w);
            accB.x = fmaf(wb.w, h3v.x, accB.x); accB.y = fmaf(wb.w, h3v.y, accB.y);
            accB.z = fmaf(wb.w, h3v.z, accB.z); accB.w = fmaf(wb.w, h3v.w, accB.w);
        }
        *(float4*)&red[w * 256 + eA * 32 + 4 * bq] = accA;
        *(float4*)&red[w * 256 + eB * 32 + 4 * bq] = accB;
        __syncthreads();

        // ---- reduce across warps + epilogue (mapping: e fastest for coalescing) ----
        {
            const int eL = tid & 7;
            const int b  = tid >> 3;
            const int o  = eL * 32 + b;
            float dot = 0.f;
            #pragma unroll
            for (int k = 0; k < 8; k++) dot += red[k * 256 + o];
            const size_t gidx = ((size_t)t * B_DIM + b) * D_DIM + (e0 + eL);
            const float wxv = wx_out[gidx];
            const float raw = wxv + dot + bsm[eL];
            const float ex  = __expf(2.f * raw);
            const float hn  = 1.f - 2.f / (ex + 1.f);        // tanh(raw)
            const float g   = wxv + hn + bgsm[eL];
            const float ov  = hn * g / (1.f + __expf(-g));    // hn * silu(g)
            wx_out[gidx] = ov;
            hout[((size_t)(t + 1) * B_DIM + b) * D_DIM + (e0 + eL)] = hn;
            hn_sm[o] = hn;
        }
        __syncthreads();

        // ---- publish next state into g_hT (d-major, coalesced) ----
        {
            const int eL2 = tid >> 5;
            const int b2  = tid & 31;
            g_hT[par ^ 1][(e0 + eL2) * B_DIM + b2] = hn_sm[eL2 * 32 + b2];
        }
        __syncthreads();

        // ---- grid barrier ----
        if (tid == 0) {
            __threadfence();
            if (atomicAdd(&g_bar_cnt, 1u) == NBLK - 1) {
                atomicExch(&g_bar_cnt, 0u);
                __threadfence();
                g_bar_gen = gen + 1;
            } else {
                while (g_bar_gen == gen) { }
            }
            gen = gen + 1;
        }
        __syncthreads();
        par ^= 1;
    }
}

// -------------------- launcher --------------------
extern "C" void kernel_launch(void* const* d_in, const int* in_sizes, int n_in,
                              void* d_out, int out_size) {
    const float* x      = (const float*)d_in[0];
    // d_in[1] = z (unused in gate_mode 0)
    const float* h0     = (const float*)d_in[2];
    const float* W_x    = (const float*)d_in[3];
    const float* W_h    = (const float*)d_in[4];
    const float* bvec   = (const float*)d_in[5];
    const float* bgvec  = (const float*)d_in[6];
    const float* u0     = (const float*)d_in[7];

    const int T = in_sizes[0] / (B_DIM * D_DIM);   // 2048
    const int M = T * B_DIM;                       // 65536

    float* out_region = (float*)d_out;                               // [T][B][D]
    float* h_region   = (float*)d_out + (size_t)T * B_DIM * D_DIM;   // [T+1][B][D]

    // 1) spectral norm scale
    spectral_kernel<<<1, 1024>>>(W_h, u0);

    // 2) prep: scaled W, transposed h0 state, h[0] copy
    prep_kernel<<<(D_DIM * D_DIM + 255) / 256, 256>>>(W_h, h0, h_region);

    // 3) feed-forward GEMM into the output region (scratch reuse)
    {
        dim3 grid(D_DIM / 128, M / 128);
        gemm_xwt_kernel<<<grid, 256>>>(x, W_x, out_region);
    }

    // 4) persistent scan
    {
        static int attr_done = -1;
        size_t smem = SMEM_FLOATS * sizeof(float);
        if (attr_done != (int)smem) {
            cudaFuncSetAttribute(scan_kernel,
                                 cudaFuncAttributeMaxDynamicSharedMemorySize,
                                 (int)smem);
            attr_done = (int)smem;
        }
        scan_kernel<<<NBLK, 256, smem>>>(out_region, h_region, bvec, bgvec, T);
    }
}

// round 6
// speedup vs baseline: 1.2317x; 1.2317x over previous
#include <cuda_runtime.h>
#include <cuda_bf16.h>
#include <math.h>
#include <stdint.h>

// Problem constants
#define D_DIM 1024
#define B_DIM 32
#define NBLK  128      // persistent scan blocks (1 CTA/SM, 128 <= 148 SMs -> all co-resident)

// -------------------- device scratch (no cudaMalloc allowed) --------------------
__device__ float g_scale;
__device__ float g_Wsc[D_DIM * D_DIM];          // W_h * scale, row-major [e][d]
__device__ float g_hT[2][D_DIM * B_DIM];        // recurrent state, d-major [d][b], double-buffered
__device__ unsigned g_bar_cnt = 0;
__device__ volatile unsigned g_bar_gen = 0;

// -------------------- block-wide sum over 1024 threads --------------------
__device__ __forceinline__ float block_sum1024(float v) {
    __shared__ float sr[32];
    __shared__ float res;
    #pragma unroll
    for (int o = 16; o; o >>= 1) v += __shfl_xor_sync(0xffffffffu, v, o);
    if ((threadIdx.x & 31) == 0) sr[threadIdx.x >> 5] = v;
    __syncthreads();
    if (threadIdx.x < 32) {
        float t = sr[threadIdx.x];
        #pragma unroll
        for (int o = 16; o; o >>= 1) t += __shfl_xor_sync(0xffffffffu, t, o);
        if (threadIdx.x == 0) res = t;
    }
    __syncthreads();
    float out = res;
    __syncthreads();
    return out;
}

// -------------------- 1) spectral norm power iteration --------------------
__global__ void spectral_kernel(const float* __restrict__ Wh,
                                const float* __restrict__ u0) {
    __shared__ float su[D_DIM];
    __shared__ float sv[D_DIM];
    __shared__ float sraw[D_DIM];
    const int tid  = threadIdx.x;
    const int w    = tid >> 5;
    const int lane = tid & 31;

    float x0 = u0[tid];
    float n0 = sqrtf(block_sum1024(x0 * x0));
    su[tid] = x0 / n0;
    __syncthreads();

    for (int it = 0; it < 3; it++) {
        {   // v = W^T u
            float a = 0.f;
            const float* col = Wh + tid;
            #pragma unroll 4
            for (int i = 0; i < D_DIM; i++)
                a = fmaf(col[(size_t)i * D_DIM], su[i], a);
            float nrm = sqrtf(block_sum1024(a * a));
            sv[tid] = a / (nrm + 1e-8f);
            __syncthreads();
        }
        {   // u_raw = W v
            for (int s = 0; s < 32; s++) {
                int r = w * 32 + s;
                const float* row = Wh + (size_t)r * D_DIM;
                float a = 0.f;
                #pragma unroll 4
                for (int k = lane; k < D_DIM; k += 32)
                    a = fmaf(row[k], sv[k], a);
                #pragma unroll
                for (int o = 16; o; o >>= 1) a += __shfl_xor_sync(0xffffffffu, a, o);
                if (lane == 0) sraw[r] = a;
            }
            __syncthreads();
            float rv  = sraw[tid];
            float nrm = sqrtf(block_sum1024(rv * rv));
            su[tid] = rv / (nrm + 1e-8f);
            __syncthreads();
        }
    }
    float sg = block_sum1024(su[tid] * sraw[tid]);
    if (tid == 0) g_scale = 0.99f / (fabsf(sg) + 1e-8f);
}

// -------------------- 2) prep --------------------
__global__ void prep_kernel(const float* __restrict__ Wh,
                            const float* __restrict__ h0,
                            float* __restrict__ hout0) {
    const float s = g_scale;
    int i = blockIdx.x * blockDim.x + threadIdx.x;
    if (i < D_DIM * D_DIM) g_Wsc[i] = Wh[i] * s;
    if (i < B_DIM * D_DIM) {
        int b = i >> 10;
        int d = i & (D_DIM - 1);
        g_hT[0][d * B_DIM + b] = h0[i];
        hout0[i] = h0[i];
    }
}

// -------------------- 3) split-tf32 tensor-core GEMM: C[m][e] = sum_d X[m][d] W[e][d] ----
// BM=BN=128, BK=32, 256 threads, 8 warps (2 m x 4 n), warp tile 64x32.
// Inputs split into tf32 hi + lo; 3 MMAs (hh, hl, lh) recover ~fp32 accuracy.
#define GS 36   // smem row stride (floats): (4*gid + tig) mod 32 distinct -> conflict-free frags

__device__ __forceinline__ void tf32_split(float v, float& h, float& l) {
    uint32_t hb; asm("cvt.rna.tf32.f32 %0, %1;" : "=r"(hb) : "f"(v));
    float hf = __uint_as_float(hb);
    float lv = v - hf;
    uint32_t lb; asm("cvt.rna.tf32.f32 %0, %1;" : "=r"(lb) : "f"(lv));
    h = hf; l = __uint_as_float(lb);
}

__device__ __forceinline__ void mma_tf32(float* c, const uint32_t* a, const uint32_t* b) {
    asm volatile(
        "mma.sync.aligned.m16n8k8.row.col.f32.tf32.tf32.f32 "
        "{%0,%1,%2,%3}, {%4,%5,%6,%7}, {%8,%9}, {%0,%1,%2,%3};"
        : "+f"(c[0]), "+f"(c[1]), "+f"(c[2]), "+f"(c[3])
        : "r"(a[0]), "r"(a[1]), "r"(a[2]), "r"(a[3]), "r"(b[0]), "r"(b[1]));
}

__global__ __launch_bounds__(256, 1)
void gemm_tf32_kernel(const float* __restrict__ X,
                      const float* __restrict__ Wg,
                      float* __restrict__ C) {
    extern __shared__ float gsm[];
    float* Xh = gsm;
    float* Xl = Xh + 128 * GS;
    float* Wh = Xl + 128 * GS;
    float* Wl = Wh + 128 * GS;

    const int tid  = threadIdx.x;
    const int bn   = blockIdx.x * 128;
    const int bm   = blockIdx.y * 128;
    const int wid  = tid >> 5, lane = tid & 31;
    const int wm   = wid >> 2;     // 0..1 : 64-row slab
    const int wn   = wid & 3;      // 0..3 : 32-col slab
    const int gid  = lane >> 2, tig = lane & 3;

    float c[4][4][4];
    #pragma unroll
    for (int mt = 0; mt < 4; mt++)
        #pragma unroll
        for (int nt = 0; nt < 4; nt++)
            #pragma unroll
            for (int r = 0; r < 4; r++) c[mt][nt][r] = 0.f;

    const int sr = tid >> 3;          // staging row 0..31
    const int sc = (tid & 7) * 4;     // staging col

    for (int k0 = 0; k0 < D_DIM; k0 += 32) {
        __syncthreads();
        #pragma unroll
        for (int j = 0; j < 4; j++) {
            int row = sr + j * 32;
            float4 xv = *(const float4*)&X[(size_t)(bm + row) * D_DIM + k0 + sc];
            float4 wv = *(const float4*)&Wg[(size_t)(bn + row) * D_DIM + k0 + sc];
            float h, l;
            tf32_split(xv.x, h, l); Xh[row*GS+sc+0]=h; Xl[row*GS+sc+0]=l;
            tf32_split(xv.y, h, l); Xh[row*GS+sc+1]=h; Xl[row*GS+sc+1]=l;
            tf32_split(xv.z, h, l); Xh[row*GS+sc+2]=h; Xl[row*GS+sc+2]=l;
            tf32_split(xv.w, h, l); Xh[row*GS+sc+3]=h; Xl[row*GS+sc+3]=l;
            tf32_split(wv.x, h, l); Wh[row*GS+sc+0]=h; Wl[row*GS+sc+0]=l;
            tf32_split(wv.y, h, l); Wh[row*GS+sc+1]=h; Wl[row*GS+sc+1]=l;
            tf32_split(wv.z, h, l); Wh[row*GS+sc+2]=h; Wl[row*GS+sc+2]=l;
            tf32_split(wv.w, h, l); Wh[row*GS+sc+3]=h; Wl[row*GS+sc+3]=l;
        }
        __syncthreads();
        #pragma unroll
        for (int k8 = 0; k8 < 4; k8++) {
            const int kk = k8 * 8 + tig;
            uint32_t ah[4][4], al[4][4], bh[4][2], bl[4][2];
            #pragma unroll
            for (int mt = 0; mt < 4; mt++) {
                int r0 = wm * 64 + mt * 16 + gid;
                const float* p0 = &Xh[r0 * GS + kk];
                ah[mt][0] = __float_as_uint(p0[0]);
                ah[mt][1] = __float_as_uint(p0[8 * GS]);
                ah[mt][2] = __float_as_uint(p0[4]);
                ah[mt][3] = __float_as_uint(p0[8 * GS + 4]);
                const float* p1 = &Xl[r0 * GS + kk];
                al[mt][0] = __float_as_uint(p1[0]);
                al[mt][1] = __float_as_uint(p1[8 * GS]);
                al[mt][2] = __float_as_uint(p1[4]);
                al[mt][3] = __float_as_uint(p1[8 * GS + 4]);
            }
            #pragma unroll
            for (int nt = 0; nt < 4; nt++) {
                int c0n = wn * 32 + nt * 8 + gid;
                const float* p0 = &Wh[c0n * GS + kk];
                bh[nt][0] = __float_as_uint(p0[0]);
                bh[nt][1] = __float_as_uint(p0[4]);
                const float* p1 = &Wl[c0n * GS + kk];
                bl[nt][0] = __float_as_uint(p1[0]);
                bl[nt][1] = __float_as_uint(p1[4]);
            }
            #pragma unroll
            for (int mt = 0; mt < 4; mt++)
                #pragma unroll
                for (int nt = 0; nt < 4; nt++) {
                    mma_tf32(c[mt][nt], ah[mt], bh[nt]);
                    mma_tf32(c[mt][nt], ah[mt], bl[nt]);
                    mma_tf32(c[mt][nt], al[mt], bh[nt]);
                }
        }
    }
    #pragma unroll
    for (int mt = 0; mt < 4; mt++) {
        int row = bm + wm * 64 + mt * 16 + gid;
        #pragma unroll
        for (int nt = 0; nt < 4; nt++) {
            int col = bn + wn * 32 + nt * 8 + 2 * tig;
            *(float2*)&C[(size_t)row * D_DIM + col]       = make_float2(c[mt][nt][0], c[mt][nt][1]);
            *(float2*)&C[(size_t)(row + 8) * D_DIM + col] = make_float2(c[mt][nt][2], c[mt][nt][3]);
        }
    }
}

// -------------------- 4) persistent scan kernel (v2) --------------------
// 128 blocks x 256 threads, block owns 8 e's (rows of W, smem-resident transposed).
// lane = bg (b-group of 8, lane&3) x dsub (lane>>2); warp covers d-chunk of 128.
// Thread tile 8e x 8b over 16 d's -> h loaded straight from L2 into registers,
// each h element read exactly once per block. Reduction over 64 partials in smem
// with bank-conflict-free layout [p][bg*65 + bi*8 + e].
#define W_STRIDE   12
#define RED_STRIDE 260
#define SCAN_SMEM_FLOATS (D_DIM * W_STRIDE + 64 * RED_STRIDE + 256 + 16)

__global__ __launch_bounds__(256, 1)
void scan_kernel(float* __restrict__ wx_out,        // [T][B][D]: in = Wx, overwritten with out
                 float* __restrict__ hout,          // [T+1][B][D]
                 const float* __restrict__ bvec,
                 const float* __restrict__ bgvec,
                 int T) {
    extern __shared__ float sm[];
    float* wT    = sm;                               // [d][W_STRIDE], e in slots 0..7
    float* red   = wT + D_DIM * W_STRIDE;            // [64][RED_STRIDE]
    float* hn_sm = red + 64 * RED_STRIDE;            // 256
    float* bsm   = hn_sm + 256;                      // 8
    float* bgsm  = bsm + 8;                          // 8

    const int tid = threadIdx.x;
    const int e0  = blockIdx.x * 8;

    // W slice, transposed: wT[d][e] = Wsc[e0+e][d]  (coalesced reads along d)
    for (int i = tid; i < 8 * D_DIM; i += 256) {
        int e = i >> 10;
        int d = i & (D_DIM - 1);
        wT[d * W_STRIDE + e] = g_Wsc[(size_t)(e0 + e) * D_DIM + d];
    }
    if (tid < 8) { bsm[tid] = bvec[e0 + tid]; bgsm[tid] = bgvec[e0 + tid]; }
    __syncthreads();

    const int w    = tid >> 5;
    const int lane = tid & 31;
    const int bg   = lane & 3;          // b in [bg*8, bg*8+8)
    const int dsub = lane >> 2;         // 0..7
    const int d0   = w * 128;
    const int p    = w * 8 + dsub;      // partial row 0..63
    const int eL   = tid & 7;           // epilogue mapping (e fast -> coalesced wx)
    const int bO   = tid >> 3;

    unsigned gen = g_bar_gen;
    int par = 0;

    for (int t = 0; t < T; t++) {
        // prefetch this thread's Wx element early (L2 latency overlaps FMA loop)
        const size_t gidx = ((size_t)t * B_DIM + bO) * D_DIM + (e0 + eL);
        const float wxv = __ldcg(&wx_out[gidx]);

        float acc[8][8];
        #pragma unroll
        for (int e = 0; e < 8; e++)
            #pragma unroll
            for (int b = 0; b < 8; b++) acc[e][b] = 0.f;

        const float4* hsrc = (const float4*)g_hT[par];
        #pragma unroll 4
        for (int i = 0; i < 16; i++) {
            const int d = d0 + dsub + 8 * i;     // warp covers contiguous 8-d groups
            float4 h0v = __ldcg(hsrc + (size_t)d * 8 + bg * 2);
            float4 h1v = __ldcg(hsrc + (size_t)d * 8 + bg * 2 + 1);
            const float* wp = wT + d * W_STRIDE;
            float4 w0v = *(const float4*)wp;
            float4 w1v = *(const float4*)(wp + 4);
            float wv[8] = {w0v.x, w0v.y, w0v.z, w0v.w, w1v.x, w1v.y, w1v.z, w1v.w};
            float hv[8] = {h0v.x, h0v.y, h0v.z, h0v.w, h1v.x, h1v.y, h1v.z, h1v.w};
            #pragma unroll
            for (int e = 0; e < 8; e++)
                #pragma unroll
                for (int b = 0; b < 8; b++)
                    acc[e][b] = fmaf(wv[e], hv[b], acc[e][b]);
        }

        // partials -> smem: bank = (4*dsub + bg) + ... all 32 lanes distinct
        #pragma unroll
        for (int e = 0; e < 8; e++)
            #pragma unroll
            for (int bi = 0; bi < 8; bi++)
                red[p * RED_STRIDE + bg * 65 + bi * 8 + e] = acc[e][bi];
        __syncthreads();

        // reduce 64 partials + epilogue; one thread per (e,b) output
        {
            const int off = (bO >> 3) * 65 + (bO & 7) * 8 + eL;
            float s0 = 0.f, s1 = 0.f, s2 = 0.f, s3 = 0.f;
            #pragma unroll
            for (int q = 0; q < 64; q += 4) {
                s0 += red[(q + 0) * RED_STRIDE + off];
                s1 += red[(q + 1) * RED_STRIDE + off];
                s2 += red[(q + 2) * RED_STRIDE + off];
                s3 += red[(q + 3) * RED_STRIDE + off];
            }
            const float dot = (s0 + s1) + (s2 + s3);
            const float raw = wxv + dot + bsm[eL];
            const float ex  = __expf(2.f * raw);
            const float hn  = 1.f - 2.f / (ex + 1.f);           // tanh(raw)
            const float g   = wxv + hn + bgsm[eL];
            const float ov  = hn * g / (1.f + __expf(-g));      // hn * silu(g)
            wx_out[gidx] = ov;
            hout[((size_t)(t + 1) * B_DIM + bO) * D_DIM + (e0 + eL)] = hn;
            hn_sm[eL * 32 + bO] = hn;
        }
        __syncthreads();

        // publish next state d-major (coalesced)
        g_hT[par ^ 1][(e0 + (tid >> 5)) * B_DIM + (tid & 31)] = hn_sm[(tid >> 5) * 32 + (tid & 31)];

        // grid barrier
        if (tid == 0) {
            __threadfence();
            if (atomicAdd(&g_bar_cnt, 1u) == NBLK - 1) {
                atomicExch(&g_bar_cnt, 0u);
                __threadfence();
                g_bar_gen = gen + 1;
            } else {
                while (g_bar_gen == gen) { }
            }
            gen = gen + 1;
        }
        __syncthreads();
        par ^= 1;
    }
}

// -------------------- launcher --------------------
extern "C" void kernel_launch(void* const* d_in, const int* in_sizes, int n_in,
                              void* d_out, int out_size) {
    const float* x      = (const float*)d_in[0];
    // d_in[1] = z (unused, gate_mode 0)
    const float* h0     = (const float*)d_in[2];
    const float* W_x    = (const float*)d_in[3];
    const float* W_h    = (const float*)d_in[4];
    const float* bvec   = (const float*)d_in[5];
    const float* bgvec  = (const float*)d_in[6];
    const float* u0     = (const float*)d_in[7];

    const int T = in_sizes[0] / (B_DIM * D_DIM);   // 2048
    const int M = T * B_DIM;                       // 65536

    float* out_region = (float*)d_out;                               // [T][B][D]
    float* h_region   = (float*)d_out + (size_t)T * B_DIM * D_DIM;   // [T+1][B][D]

    const size_t scan_smem = SCAN_SMEM_FLOATS * sizeof(float);       // 116800 B
    const size_t gemm_smem = 4 * 128 * GS * sizeof(float);           // 73728 B

    static bool attrs_set = false;
    if (!attrs_set) {
        cudaFuncSetAttribute(scan_kernel,
                             cudaFuncAttributeMaxDynamicSharedMemorySize, (int)scan_smem);
        cudaFuncSetAttribute(gemm_tf32_kernel,
                             cudaFuncAttributeMaxDynamicSharedMemorySize, (int)gemm_smem);
        attrs_set = true;
    }

    spectral_kernel<<<1, 1024>>>(W_h, u0);
    prep_kernel<<<(D_DIM * D_DIM + 255) / 256, 256>>>(W_h, h0, h_region);

    {
        dim3 grid(D_DIM / 128, M / 128);
        gemm_tf32_kernel<<<grid, 256, gemm_smem>>>(x, W_x, out_region);
    }

    scan_kernel<<<NBLK, 256, scan_smem>>>(out_region, h_region, bvec, bgvec, T);
}

// round 7
// speedup vs baseline: 1.3899x; 1.1284x over previous
#include <cuda_runtime.h>
#include <cuda_bf16.h>
#include <math.h>
#include <stdint.h>

// Problem constants
#define D_DIM 1024
#define B_DIM 32
#define NBLK  128      // 4 groups x 32 blocks, 1 CTA/SM, all co-resident
#define NGROUP 4
#define GSZ    32      // blocks per group
#define BSUB   8       // batches per group

// -------------------- device scratch (no cudaMalloc allowed) --------------------
__device__ float g_scale;
__device__ float g_Wsc[D_DIM * D_DIM];             // W_h * scale, row-major [e][d]
__device__ float g_state[NGROUP][2][D_DIM * BSUB]; // per-group state, [d][b_sub], double-buffered
__device__ unsigned g_cnt[NGROUP * 32];            // per-group barrier counters (128B apart)
__device__ volatile unsigned g_genv[NGROUP * 32];  // per-group barrier generations

// -------------------- block-wide sum over 1024 threads --------------------
__device__ __forceinline__ float block_sum1024(float v) {
    __shared__ float sr[32];
    __shared__ float res;
    #pragma unroll
    for (int o = 16; o; o >>= 1) v += __shfl_xor_sync(0xffffffffu, v, o);
    if ((threadIdx.x & 31) == 0) sr[threadIdx.x >> 5] = v;
    __syncthreads();
    if (threadIdx.x < 32) {
        float t = sr[threadIdx.x];
        #pragma unroll
        for (int o = 16; o; o >>= 1) t += __shfl_xor_sync(0xffffffffu, t, o);
        if (threadIdx.x == 0) res = t;
    }
    __syncthreads();
    float out = res;
    __syncthreads();
    return out;
}

// -------------------- 1) spectral norm power iteration --------------------
__global__ void spectral_kernel(const float* __restrict__ Wh,
                                const float* __restrict__ u0) {
    __shared__ float su[D_DIM];
    __shared__ float sv[D_DIM];
    __shared__ float sraw[D_DIM];
    const int tid  = threadIdx.x;
    const int w    = tid >> 5;
    const int lane = tid & 31;

    float x0 = u0[tid];
    float n0 = sqrtf(block_sum1024(x0 * x0));
    su[tid] = x0 / n0;
    __syncthreads();

    for (int it = 0; it < 3; it++) {
        {   // v = W^T u
            float a = 0.f;
            const float* col = Wh + tid;
            #pragma unroll 4
            for (int i = 0; i < D_DIM; i++)
                a = fmaf(col[(size_t)i * D_DIM], su[i], a);
            float nrm = sqrtf(block_sum1024(a * a));
            sv[tid] = a / (nrm + 1e-8f);
            __syncthreads();
        }
        {   // u_raw = W v
            for (int s = 0; s < 32; s++) {
                int r = w * 32 + s;
                const float* row = Wh + (size_t)r * D_DIM;
                float a = 0.f;
                #pragma unroll 4
                for (int k = lane; k < D_DIM; k += 32)
                    a = fmaf(row[k], sv[k], a);
                #pragma unroll
                for (int o = 16; o; o >>= 1) a += __shfl_xor_sync(0xffffffffu, a, o);
                if (lane == 0) sraw[r] = a;
            }
            __syncthreads();
            float rv  = sraw[tid];
            float nrm = sqrtf(block_sum1024(rv * rv));
            su[tid] = rv / (nrm + 1e-8f);
            __syncthreads();
        }
    }
    float sg = block_sum1024(su[tid] * sraw[tid]);
    if (tid == 0) g_scale = 0.99f / (fabsf(sg) + 1e-8f);
}

// -------------------- 2) prep --------------------
__global__ void prep_kernel(const float* __restrict__ Wh,
                            const float* __restrict__ h0,
                            float* __restrict__ hout0) {
    const float s = g_scale;
    int i = blockIdx.x * blockDim.x + threadIdx.x;
    if (i < D_DIM * D_DIM) g_Wsc[i] = Wh[i] * s;
    if (i < B_DIM * D_DIM) {
        int b = i >> 10;
        int d = i & (D_DIM - 1);
        g_state[b >> 3][0][d * BSUB + (b & 7)] = h0[i];
        hout0[i] = h0[i];
    }
}

// -------------------- 3) split-tf32 tensor-core GEMM: C[m][e] = sum_d X[m][d] W[e][d] ----
#define GS 36

__device__ __forceinline__ void tf32_split(float v, float& h, float& l) {
    uint32_t hb; asm("cvt.rna.tf32.f32 %0, %1;" : "=r"(hb) : "f"(v));
    float hf = __uint_as_float(hb);
    float lv = v - hf;
    uint32_t lb; asm("cvt.rna.tf32.f32 %0, %1;" : "=r"(lb) : "f"(lv));
    h = hf; l = __uint_as_float(lb);
}

__device__ __forceinline__ void mma_tf32(float* c, const uint32_t* a, const uint32_t* b) {
    asm volatile(
        "mma.sync.aligned.m16n8k8.row.col.f32.tf32.tf32.f32 "
        "{%0,%1,%2,%3}, {%4,%5,%6,%7}, {%8,%9}, {%0,%1,%2,%3};"
        : "+f"(c[0]), "+f"(c[1]), "+f"(c[2]), "+f"(c[3])
        : "r"(a[0]), "r"(a[1]), "r"(a[2]), "r"(a[3]), "r"(b[0]), "r"(b[1]));
}

__global__ __launch_bounds__(256, 1)
void gemm_tf32_kernel(const float* __restrict__ X,
                      const float* __restrict__ Wg,
                      float* __restrict__ C) {
    extern __shared__ float gsm[];
    float* Xh = gsm;
    float* Xl = Xh + 128 * GS;
    float* Wh = Xl + 128 * GS;
    float* Wl = Wh + 128 * GS;

    const int tid  = threadIdx.x;
    const int bn   = blockIdx.x * 128;
    const int bm   = blockIdx.y * 128;
    const int wid  = tid >> 5, lane = tid & 31;
    const int wm   = wid >> 2;
    const int wn   = wid & 3;
    const int gid  = lane >> 2, tig = lane & 3;

    float c[4][4][4];
    #pragma unroll
    for (int mt = 0; mt < 4; mt++)
        #pragma unroll
        for (int nt = 0; nt < 4; nt++)
            #pragma unroll
            for (int r = 0; r < 4; r++) c[mt][nt][r] = 0.f;

    const int sr = tid >> 3;
    const int sc = (tid & 7) * 4;

    for (int k0 = 0; k0 < D_DIM; k0 += 32) {
        __syncthreads();
        #pragma unroll
        for (int j = 0; j < 4; j++) {
            int row = sr + j * 32;
            float4 xv = *(const float4*)&X[(size_t)(bm + row) * D_DIM + k0 + sc];
            float4 wv = *(const float4*)&Wg[(size_t)(bn + row) * D_DIM + k0 + sc];
            float h, l;
            tf32_split(xv.x, h, l); Xh[row*GS+sc+0]=h; Xl[row*GS+sc+0]=l;
            tf32_split(xv.y, h, l); Xh[row*GS+sc+1]=h; Xl[row*GS+sc+1]=l;
            tf32_split(xv.z, h, l); Xh[row*GS+sc+2]=h; Xl[row*GS+sc+2]=l;
            tf32_split(xv.w, h, l); Xh[row*GS+sc+3]=h; Xl[row*GS+sc+3]=l;
            tf32_split(wv.x, h, l); Wh[row*GS+sc+0]=h; Wl[row*GS+sc+0]=l;
            tf32_split(wv.y, h, l); Wh[row*GS+sc+1]=h; Wl[row*GS+sc+1]=l;
            tf32_split(wv.z, h, l); Wh[row*GS+sc+2]=h; Wl[row*GS+sc+2]=l;
            tf32_split(wv.w, h, l); Wh[row*GS+sc+3]=h; Wl[row*GS+sc+3]=l;
        }
        __syncthreads();
        #pragma unroll
        for (int k8 = 0; k8 < 4; k8++) {
            const int kk = k8 * 8 + tig;
            uint32_t ah[4][4], al[4][4], bh[4][2], bl[4][2];
            #pragma unroll
            for (int mt = 0; mt < 4; mt++) {
                int r0 = wm * 64 + mt * 16 + gid;
                const float* p0 = &Xh[r0 * GS + kk];
                ah[mt][0] = __float_as_uint(p0[0]);
                ah[mt][1] = __float_as_uint(p0[8 * GS]);
                ah[mt][2] = __float_as_uint(p0[4]);
                ah[mt][3] = __float_as_uint(p0[8 * GS + 4]);
                const float* p1 = &Xl[r0 * GS + kk];
                al[mt][0] = __float_as_uint(p1[0]);
                al[mt][1] = __float_as_uint(p1[8 * GS]);
                al[mt][2] = __float_as_uint(p1[4]);
                al[mt][3] = __float_as_uint(p1[8 * GS + 4]);
            }
            #pragma unroll
            for (int nt = 0; nt < 4; nt++) {
                int c0n = wn * 32 + nt * 8 + gid;
                const float* p0 = &Wh[c0n * GS + kk];
                bh[nt][0] = __float_as_uint(p0[0]);
                bh[nt][1] = __float_as_uint(p0[4]);
                const float* p1 = &Wl[c0n * GS + kk];
                bl[nt][0] = __float_as_uint(p1[0]);
                bl[nt][1] = __float_as_uint(p1[4]);
            }
            #pragma unroll
            for (int mt = 0; mt < 4; mt++)
                #pragma unroll
                for (int nt = 0; nt < 4; nt++) {
                    mma_tf32(c[mt][nt], ah[mt], bh[nt]);
                    mma_tf32(c[mt][nt], ah[mt], bl[nt]);
                    mma_tf32(c[mt][nt], al[mt], bh[nt]);
                }
        }
    }
    #pragma unroll
    for (int mt = 0; mt < 4; mt++) {
        int row = bm + wm * 64 + mt * 16 + gid;
        #pragma unroll
        for (int nt = 0; nt < 4; nt++) {
            int col = bn + wn * 32 + nt * 8 + 2 * tig;
            *(float2*)&C[(size_t)row * D_DIM + col]       = make_float2(c[mt][nt][0], c[mt][nt][1]);
            *(float2*)&C[(size_t)(row + 8) * D_DIM + col] = make_float2(c[mt][nt][2], c[mt][nt][3]);
        }
    }
}

// -------------------- 4) persistent scan kernel (v3: 4 independent groups) ----------
// Group g (32 blocks) owns batches [8g, 8g+8). Block owns 32 e's; W slice (32x1024)
// smem-resident transposed (stride 36, conflict-free frag loads). Warp w covers d-chunk
// of 128; lane = eg*8 + dsub; thread tile 8e (eg) x 8b (all) over 16 d's.
// Partials stored transposed red[o=b*32+e][(p + 8*eg) & 63], stride 68 -> conflict-free
// scalar stores AND conflict-free float4 reduce loads.
#define W_STRIDE 36
#define RED_STRIDE 68
#define SCAN_SMEM_FLOATS (D_DIM * W_STRIDE + 256 * RED_STRIDE + 32 * 9 + 32 + 32)

__global__ __launch_bounds__(256, 1)
void scan_kernel(float* __restrict__ wx_out,        // [T][B][D]: in = Wx, overwritten with out
                 float* __restrict__ hout,          // [T+1][B][D]
                 const float* __restrict__ bvec,
                 const float* __restrict__ bgvec,
                 int T) {
    extern __shared__ float sm[];
    float* wT    = sm;                               // [d][W_STRIDE], e in slots 0..31
    float* red   = wT + D_DIM * W_STRIDE;            // [256][RED_STRIDE]
    float* hn_sm = red + 256 * RED_STRIDE;           // 32*9
    float* bsm   = hn_sm + 32 * 9;                   // 32
    float* bgsm  = bsm + 32;                         // 32

    const int tid = threadIdx.x;
    const int g   = blockIdx.x >> 5;     // group 0..3
    const int r   = blockIdx.x & 31;     // rank in group
    const int e0  = r * 32;
    const int b0  = g * BSUB;
    const int bar = g * 32;              // barrier slot

    // W slice transposed into smem: wT[d*36 + e] = Wsc[e0+e][d]
    for (int i = tid; i < 32 * D_DIM; i += 256) {
        int e = i >> 10;
        int d = i & (D_DIM - 1);
        wT[d * W_STRIDE + e] = g_Wsc[(size_t)(e0 + e) * D_DIM + d];
    }
    if (tid < 32) { bsm[tid] = bvec[e0 + tid]; bgsm[tid] = bgvec[e0 + tid]; }
    __syncthreads();

    const int w    = tid >> 5;
    const int lane = tid & 31;
    const int eg   = lane >> 3;          // 0..3 : which 8 e's
    const int dsub = lane & 7;           // 0..7
    const int d0   = w * 128;
    const int pcol = ((w * 8 + dsub) + 8 * eg) & 63;   // rotated partial column
    const int eL   = tid & 31;           // epilogue: e (coalesced wx/hout)
    const int bO   = tid >> 5;           // epilogue: batch within group (0..7)
    const int rrow = (bO * 32 + eL) * RED_STRIDE;
    const int rrot = (eL >> 3) * 8;      // reduce-side rotation (8*eg of output e)

    unsigned gen = g_genv[bar];
    int par = 0;

    for (int t = 0; t < T; t++) {
        // prefetch this thread's Wx element (L2 latency overlaps FMA loop)
        const size_t gidx = ((size_t)t * B_DIM + (b0 + bO)) * D_DIM + (e0 + eL);
        const float wxv = __ldcg(&wx_out[gidx]);

        float acc[8][8];
        #pragma unroll
        for (int e = 0; e < 8; e++)
            #pragma unroll
            for (int b = 0; b < 8; b++) acc[e][b] = 0.f;

        const float4* hsrc = (const float4*)g_state[g][par];
        #pragma unroll 4
        for (int i = 0; i < 16; i++) {
            const int d = d0 + dsub + 8 * i;
            float4 h0v = __ldcg(hsrc + (size_t)d * 2);
            float4 h1v = __ldcg(hsrc + (size_t)d * 2 + 1);
            const float* wp = wT + d * W_STRIDE + eg * 8;
            float4 w0v = *(const float4*)wp;
            float4 w1v = *(const float4*)(wp + 4);
            float wv[8] = {w0v.x, w0v.y, w0v.z, w0v.w, w1v.x, w1v.y, w1v.z, w1v.w};
            float hv[8] = {h0v.x, h0v.y, h0v.z, h0v.w, h1v.x, h1v.y, h1v.z, h1v.w};
            #pragma unroll
            for (int e = 0; e < 8; e++)
                #pragma unroll
                for (int b = 0; b < 8; b++)
                    acc[e][b] = fmaf(wv[e], hv[b], acc[e][b]);
        }

        // partials -> red[o][pcol], o = b*32 + eg*8 + ei  (conflict-free scalar STS)
        #pragma unroll
        for (int ei = 0; ei < 8; ei++)
            #pragma unroll
            for (int b = 0; b < 8; b++)
                red[(b * 32 + eg * 8 + ei) * RED_STRIDE + pcol] = acc[ei][b];
        __syncthreads();

        // reduce 64 partials with conflict-free float4 loads + epilogue
        {
            float s0 = 0.f, s1 = 0.f, s2 = 0.f, s3 = 0.f;
            #pragma unroll
            for (int q = 0; q < 16; q += 4) {
                float4 v0 = *(const float4*)&red[rrow + ((4 * (q + 0) + rrot) & 63)];
                float4 v1 = *(const float4*)&red[rrow + ((4 * (q + 1) + rrot) & 63)];
                float4 v2 = *(const float4*)&red[rrow + ((4 * (q + 2) + rrot) & 63)];
                float4 v3 = *(const float4*)&red[rrow + ((4 * (q + 3) + rrot) & 63)];
                s0 += v0.x + v0.y + v0.z + v0.w;
                s1 += v1.x + v1.y + v1.z + v1.w;
                s2 += v2.x + v2.y + v2.z + v2.w;
                s3 += v3.x + v3.y + v3.z + v3.w;
            }
            const float dot = (s0 + s1) + (s2 + s3);
            const float raw = wxv + dot + bsm[eL];
            const float ex  = __expf(2.f * raw);
            const float hn  = 1.f - 2.f / (ex + 1.f);           // tanh(raw)
            const float gg  = wxv + hn + bgsm[eL];
            const float ov  = hn * gg / (1.f + __expf(-gg));    // hn * silu(gg)
            wx_out[gidx] = ov;                                   // fire-and-forget stores
            hout[((size_t)(t + 1) * B_DIM + (b0 + bO)) * D_DIM + (e0 + eL)] = hn;
            hn_sm[eL * 9 + bO] = hn;                             // conflict-free (9*eL distinct mod 32)
        }
        __syncthreads();

        // publish next state: contiguous coalesced 1KB; conflict-free hn_sm reads
        g_state[g][par ^ 1][e0 * BSUB + tid] = hn_sm[(tid >> 3) * 9 + (tid & 7)];
        __syncthreads();

        // per-group barrier
        if (tid == 0) {
            __threadfence();
            if (atomicAdd(&g_cnt[bar], 1u) == GSZ - 1) {
                atomicExch(&g_cnt[bar], 0u);
                __threadfence();
                g_genv[bar] = gen + 1;
            } else {
                while (g_genv[bar] == gen) { }
            }
            gen = gen + 1;
        }
        __syncthreads();
        par ^= 1;
    }
}

// -------------------- launcher --------------------
extern "C" void kernel_launch(void* const* d_in, const int* in_sizes, int n_in,
                              void* d_out, int out_size) {
    const float* x      = (const float*)d_in[0];
    // d_in[1] = z (unused, gate_mode 0)
    const float* h0     = (const float*)d_in[2];
    const float* W_x    = (const float*)d_in[3];
    const float* W_h    = (const float*)d_in[4];
    const float* bvec   = (const float*)d_in[5];
    const float* bgvec  = (const float*)d_in[6];
    const float* u0     = (const float*)d_in[7];

    const int T = in_sizes[0] / (B_DIM * D_DIM);   // 2048
    const int M = T * B_DIM;                       // 65536

    float* out_region = (float*)d_out;                               // [T][B][D]
    float* h_region   = (float*)d_out + (size_t)T * B_DIM * D_DIM;   // [T+1][B][D]

    const size_t scan_smem = SCAN_SMEM_FLOATS * sizeof(float);       // ~218.6 KB
    const size_t gemm_smem = 4 * 128 * GS * sizeof(float);           // 73728 B

    static bool attrs_set = false;
    if (!attrs_set) {
        cudaFuncSetAttribute(scan_kernel,
                             cudaFuncAttributeMaxDynamicSharedMemorySize, (int)scan_smem);
        cudaFuncSetAttribute(gemm_tf32_kernel,
                             cudaFuncAttributeMaxDynamicSharedMemorySize, (int)gemm_smem);
        attrs_set = true;
    }

    spectral_kernel<<<1, 1024>>>(W_h, u0);
    prep_kernel<<<(D_DIM * D_DIM + 255) / 256, 256>>>(W_h, h0, h_region);

    {
        dim3 grid(D_DIM / 128, M / 128);
        gemm_tf32_kernel<<<grid, 256, gemm_smem>>>(x, W_x, out_region);
    }

    scan_kernel<<<NBLK, 256, scan_smem>>>(out_region, h_region, bvec, bgvec, T);
}